// round 10
// baseline (speedup 1.0000x reference)
#include <cuda_runtime.h>
#include <cmath>

#define CF 22
#define IPAD 24
#define KPAD 24
#define NM 9
#define TILE_W 16
#define TILE_H 8
#define NT 128

typedef unsigned long long ull;

// Precomputed weighted tensors (prep kernel output)
__device__ float gWtp[CF * CF * IPAD];  // [k][j][i24]
__device__ float gK[NM * CF * KPAD];    // [m][i][k24]

// ---- packed f32x2 helpers (Blackwell FFMA2 path; only reachable via PTX) ----
__device__ __forceinline__ ull pk2(float lo, float hi) {
    ull r; asm("mov.b64 %0, {%1,%2};" : "=l"(r) : "f"(lo), "f"(hi)); return r;
}
__device__ __forceinline__ void upk2(ull v, float& a, float& b) {
    asm("mov.b64 {%0,%1}, %2;" : "=f"(a), "=f"(b) : "l"(v));
}
__device__ __forceinline__ ull pdup(float x) {
    ull r; asm("mov.b64 %0, {%1,%1};" : "=l"(r) : "f"(x)); return r;
}
__device__ __forceinline__ ull pfma(ull a, ull b, ull c) {
    ull r; asm("fma.rn.f32x2 %0, %1, %2, %3;" : "=l"(r) : "l"(a), "l"(b), "l"(c)); return r;
}
__device__ __forceinline__ ull pmul(ull a, ull b) {
    ull r; asm("mul.rn.f32x2 %0, %1, %2;" : "=l"(r) : "l"(a), "l"(b)); return r;
}
__device__ __forceinline__ ull padd(ull a, ull b) {
    ull r; asm("add.rn.f32x2 %0, %1, %2;" : "=l"(r) : "l"(a), "l"(b)); return r;
}

// ============================================================================
// Prep: fold learned weights into Wtp and the 9 context matrices.
// m: 0:K0+K1+K2+K3  1:K0+K2  2:K0+K1  3:K0  4:K1+K3  5:K1  6:K2+K3  7:K2  8:K3
// ============================================================================
__global__ void prep_kernel(const float* __restrict__ sh,
                            const float* __restrict__ cg_agg,
                            const float* __restrict__ cg_tp,
                            const float* __restrict__ w_agg,
                            const float* __restrict__ w_tp) {
    int gtid = blockIdx.x * blockDim.x + threadIdx.x;
    int nthr = gridDim.x * blockDim.x;
    for (int idx = gtid; idx < CF * CF * IPAD; idx += nthr) {
        int k = idx / (CF * IPAD);
        int r = idx - k * CF * IPAD;
        int j = r / IPAD;
        int i = r - j * IPAD;
        float v = 0.f;
        if (i < CF) {
            #pragma unroll
            for (int p = 0; p < 8; p++)
                v += w_tp[p] * cg_tp[((p * CF + i) * CF + j) * CF + k];
        }
        gWtp[idx] = v;
    }
    for (int idx = gtid; idx < CF * KPAD; idx += nthr) {
        int i = idx / KPAD;
        int k = idx - i * KPAD;
        float K0 = 0.f, K1 = 0.f, K2 = 0.f, K3 = 0.f;
        if (k < CF) {
            #pragma unroll
            for (int s = 0; s < 6; s++) {
                float wa = 0.f;
                #pragma unroll
                for (int p = 0; p < 6; p++)
                    wa += w_agg[p] * cg_agg[((p * CF + i) * 6 + s) * CF + k];
                K0 += wa * sh[0 * 6 + s];
                K1 += wa * sh[1 * 6 + s];
                K2 += wa * sh[2 * 6 + s];
                K3 += wa * sh[3 * 6 + s];
            }
        }
        gK[(0 * CF + i) * KPAD + k] = K0 + K1 + K2 + K3;
        gK[(1 * CF + i) * KPAD + k] = K0 + K2;
        gK[(2 * CF + i) * KPAD + k] = K0 + K1;
        gK[(3 * CF + i) * KPAD + k] = K0;
        gK[(4 * CF + i) * KPAD + k] = K1 + K3;
        gK[(5 * CF + i) * KPAD + k] = K1;
        gK[(6 * CF + i) * KPAD + k] = K2 + K3;
        gK[(7 * CF + i) * KPAD + k] = K2;
        gK[(8 * CF + i) * KPAD + k] = K3;
    }
}

// Context accumulation pass: ctx2[CAT][*] += src[i] * sK[m][i][*]
template <int CAT>
__device__ __forceinline__ void ctx_pass(ull (&ctx2)[4][11], const ulonglong2* sK2,
                                         const float* src, int m) {
    #pragma unroll 2
    for (int i = 0; i < CF; i++) {
        ull fi2 = pdup(src[i]);
        const ulonglong2* row = sK2 + (m * CF + i) * 6;
        #pragma unroll
        for (int c = 0; c < 5; c++) {
            ulonglong2 t = row[c];
            ctx2[CAT][2 * c]     = pfma(fi2, t.x, ctx2[CAT][2 * c]);
            ctx2[CAT][2 * c + 1] = pfma(fi2, t.y, ctx2[CAT][2 * c + 1]);
        }
        ull t10 = row[5].x;
        ctx2[CAT][10] = pfma(fi2, t10, ctx2[CAT][10]);
    }
}

// ============================================================================
// Main kernel (R9 + packed ctx-pair bilinear accumulation):
//   smem = sW (45.4KB) + sK (18.6KB) + stage (44.5KB) + tables (2.8KB)
//        = 111.2KB -> 2 blocks/SM.
//   Bilinear per (k,j): 6 LDS.128 + 11 FFMA2 + reduce + 2 packed cat-FMAs
//   (ctx pre-packed as (cat0,cat1)/(cat2,cat3) pairs in 88 regs).
//   Drain: table-driven, no div, no LDG (residual folded into the stage).
// ============================================================================
__global__ void __launch_bounds__(NT, 2)
main_kernel(const float* __restrict__ f4, const float* __restrict__ f6,
            float* __restrict__ out, int H, int W) {
    extern __shared__ float smem[];
    float* sW = smem;                      // CF*CF*IPAD
    float* sK = smem + CF * CF * IPAD;     // NM*CF*KPAD
    float* stg = sK + NM * CF * KPAD;      // NT*89 (stride 89 -> conflict-free)
    unsigned short* tbl4 = (unsigned short*)(stg + NT * 89);  // 576 entries
    unsigned short* tbl6 = tbl4 + 576;                        // 832 entries
    const int tid = threadIdx.x;

    for (int idx = tid; idx < CF * CF * IPAD; idx += NT) sW[idx] = gWtp[idx];
    for (int idx = tid; idx < NM * CF * KPAD; idx += NT) sK[idx] = gK[idx];
    // index tables: stage offset for each element of one hi-res row image
    for (int ee = tid; ee < 576; ee += NT) {
        int px = ee / 9;
        int c = ee - px * 9;
        int b = px & 3;
        int lxr = px >> 2;
        int cat = (b < 3) ? 0 : 1;   // a==3 rows: same entry + 44 (cat 2/3)
        tbl4[ee] = (unsigned short)(lxr * 89 + cat * CF + c);
    }
    for (int ee = tid; ee < 832; ee += NT) {
        int px = ee / 13;
        int c = ee - px * 13;
        int b = px & 3;
        int lxr = px >> 2;
        int cat = (b < 3) ? 0 : 1;
        tbl6[ee] = (unsigned short)(lxr * 89 + cat * CF + 9 + c);
    }
    __syncthreads();

    const int tiles_x = W / TILE_W;
    const int tx0 = (blockIdx.x % tiles_x) * TILE_W;
    const int ty0 = (blockIdx.x / tiles_x) * TILE_H;
    const int lx = tid % TILE_W;
    const int ly = tid / TILE_W;
    const int w0 = tx0 + lx;
    const int h0 = ty0 + ly;
    const int wR = min(w0 + 1, W - 1);
    const int hD = min(h0 + 1, H - 1);
    const int p00 = h0 * W + w0;
    const int p01 = h0 * W + wR;
    const int p10 = hD * W + w0;
    const int p11 = hD * W + wR;

    // ---- preload features: self -> packed regs, all 4 sources -> per-thread stage ----
    float* myst = stg + tid * 89;
    ull f2[11];
    {
        float xv[CF];
        #pragma unroll
        for (int c = 0; c < CF; c++) {
            xv[c] = (c < 9) ? f4[p00 * 9 + c] : f6[p00 * 13 + (c - 9)];
            myst[c] = xv[c];
        }
        #pragma unroll
        for (int kk = 0; kk < 11; kk++) f2[kk] = pk2(xv[2 * kk], xv[2 * kk + 1]);
        #pragma unroll
        for (int c = 0; c < CF; c++) {
            myst[1 * CF + c] = (c < 9) ? f4[p01 * 9 + c] : f6[p01 * 13 + (c - 9)];
            myst[2 * CF + c] = (c < 9) ? f4[p10 * 9 + c] : f6[p10 * 13 + (c - 9)];
            myst[3 * CF + c] = (c < 9) ? f4[p11 * 9 + c] : f6[p11 * 13 + (c - 9)];
        }
    }

    // ---- 4 context vectors (cat 0:interior 1:right-edge 2:bottom-edge 3:corner) ----
    ull ctx2[4][11];
    #pragma unroll
    for (int c4 = 0; c4 < 4; c4++)
        #pragma unroll
        for (int kk = 0; kk < 11; kk++) ctx2[c4][kk] = 0ULL;

    const ulonglong2* sK2 = (const ulonglong2*)sK;
    ctx_pass<0>(ctx2, sK2, myst, 0);
    ctx_pass<1>(ctx2, sK2, myst, 1);
    ctx_pass<2>(ctx2, sK2, myst, 2);
    ctx_pass<3>(ctx2, sK2, myst, 3);
    ctx_pass<1>(ctx2, sK2, myst + CF, 4);
    ctx_pass<3>(ctx2, sK2, myst + CF, 5);
    ctx_pass<2>(ctx2, sK2, myst + 2 * CF, 6);
    ctx_pass<3>(ctx2, sK2, myst + 2 * CF, 7);
    ctx_pass<3>(ctx2, sK2, myst + 3 * CF, 8);

    // repack ctx as (cat0,cat1) / (cat2,cat3) f32x2 pairs per j (44 ull)
    ull ctxp01[CF], ctxp23[CF];
    #pragma unroll
    for (int kk = 0; kk < 11; kk++) {
        float c0a, c0b, c1a, c1b, c2a, c2b, c3a, c3b;
        upk2(ctx2[0][kk], c0a, c0b);
        upk2(ctx2[1][kk], c1a, c1b);
        upk2(ctx2[2][kk], c2a, c2b);
        upk2(ctx2[3][kk], c3a, c3b);
        ctxp01[2 * kk]     = pk2(c0a, c1a);
        ctxp01[2 * kk + 1] = pk2(c0b, c1b);
        ctxp23[2 * kk]     = pk2(c2a, c3a);
        ctxp23[2 * kk + 1] = pk2(c2b, c3b);
    }

    // ---- bilinear: out_cat[k] = sum_j ctx[cat][j]*(sum_i f[i]*W[k][j][i]) + f[k] ----
    const ulonglong2* sW2 = (const ulonglong2*)sW;
    #pragma unroll 1
    for (int k = 0; k < CF; k++) {
        ull o01 = 0ULL, o23 = 0ULL;
        const ulonglong2* wbase = sW2 + k * (CF * 6);
        #pragma unroll
        for (int j = 0; j < CF; j++) {
            const ulonglong2* wr = wbase + j * 6;
            ulonglong2 t0 = wr[0], t1 = wr[1], t2 = wr[2];
            ull va = pmul(f2[0], t0.x);
            ull vb = pmul(f2[1], t0.y);
            va = pfma(f2[2], t1.x, va);
            vb = pfma(f2[3], t1.y, vb);
            va = pfma(f2[4], t2.x, va);
            vb = pfma(f2[5], t2.y, vb);
            ulonglong2 t3 = wr[3], t4 = wr[4];
            ull t10 = wr[5].x;
            va = pfma(f2[6], t3.x, va);
            vb = pfma(f2[7], t3.y, vb);
            va = pfma(f2[8], t4.x, va);
            vb = pfma(f2[9], t4.y, vb);
            va = pfma(f2[10], t10, va);
            ull vp = padd(va, vb);
            float a, b;
            upk2(vp, a, b);
            ull vd = pdup(a + b);
            o01 = pfma(vd, ctxp01[j], o01);
            o23 = pfma(vd, ctxp23[j], o23);
        }
        // residual fold: self feature k is still resident in myst[k]
        float xk = myst[k];
        float a0, a1, a2, a3;
        upk2(o01, a0, a1);
        upk2(o23, a2, a3);
        myst[0 * CF + k] = a0 + xk;
        myst[1 * CF + k] = a1 + xk;
        myst[2 * CF + k] = a2 + xk;
        myst[3 * CF + k] = a3 + xk;
    }
    __syncthreads();

    // ---- table-driven drain: pure smem->gmem copy, no div, no LDG ----
    const int Wr = W * 4;
    {   // out4: 64 px * 9 floats = 144 float4 per hi-res row
        const int QR = 144;
        for (int idx = tid; idx < TILE_H * 4 * QR; idx += NT) {
            int y = idx / QR;
            int q = idx - y * QR;
            int py = y >> 2;
            int base = py * (TILE_W * 89) + (((y & 3) == 3) ? 2 * CF : 0);
            ushort4 tb = *(const ushort4*)(tbl4 + q * 4);
            float4 v = make_float4(stg[base + tb.x], stg[base + tb.y],
                                   stg[base + tb.z], stg[base + tb.w]);
            int gy = ty0 * 4 + y;
            float4* dst = (float4*)(out + ((size_t)gy * Wr + (size_t)tx0 * 4) * 9);
            dst[q] = v;
        }
    }
    {   // out6: 64 px * 13 floats = 208 float4 per hi-res row
        const size_t N9 = (size_t)H * W * 16 * 9;
        const int QR = 208;
        for (int idx = tid; idx < TILE_H * 4 * QR; idx += NT) {
            int y = idx / QR;
            int q = idx - y * QR;
            int py = y >> 2;
            int base = py * (TILE_W * 89) + (((y & 3) == 3) ? 2 * CF : 0);
            ushort4 tb = *(const ushort4*)(tbl6 + q * 4);
            float4 v = make_float4(stg[base + tb.x], stg[base + tb.y],
                                   stg[base + tb.z], stg[base + tb.w]);
            int gy = ty0 * 4 + y;
            float4* dst = (float4*)(out + N9 + ((size_t)gy * Wr + (size_t)tx0 * 4) * 13);
            dst[q] = v;
        }
    }
}

extern "C" void kernel_launch(void* const* d_in, const int* in_sizes, int n_in,
                              void* d_out, int out_size) {
    const float* f4     = (const float*)d_in[0];
    const float* f6     = (const float*)d_in[1];
    const float* sh     = (const float*)d_in[2];
    const float* cg_agg = (const float*)d_in[3];
    const float* cg_tp  = (const float*)d_in[4];
    const float* w_agg  = (const float*)d_in[5];
    const float* w_tp   = (const float*)d_in[6];
    float* out = (float*)d_out;

    int HW = in_sizes[0] / 9;
    int W = (int)(sqrt((double)HW) + 0.5);
    int H = HW / W;

    prep_kernel<<<96, 128>>>(sh, cg_agg, cg_tp, w_agg, w_tp);

    // floats: sW 11616 + sK 4752 + stage 11392, then 1408 ushorts (704 floats)
    int smemB = (CF * CF * IPAD + NM * CF * KPAD + NT * 89 + 704) * (int)sizeof(float);
    cudaFuncSetAttribute(main_kernel, cudaFuncAttributeMaxDynamicSharedMemorySize, smemB);
    int nblocks = HW / NT;
    main_kernel<<<nblocks, NT, smemB>>>(f4, f6, out, H, W);
}

// round 12
// speedup vs baseline: 1.0318x; 1.0318x over previous
#include <cuda_runtime.h>
#include <cmath>

#define CF 22
#define IPAD 24
#define KPAD 24
#define NM 9
#define TILE_W 16
#define TILE_H 8
#define NT 128

typedef unsigned long long ull;

// Precomputed weighted tensors (prep kernel output)
__device__ float gWtp[CF * CF * IPAD];  // [k][j][i24]
__device__ float gK[NM * CF * KPAD];    // [m][i][k24]

// ---- packed f32x2 helpers (Blackwell FFMA2 path; only reachable via PTX) ----
__device__ __forceinline__ ull pk2(float lo, float hi) {
    ull r; asm("mov.b64 %0, {%1,%2};" : "=l"(r) : "f"(lo), "f"(hi)); return r;
}
__device__ __forceinline__ void upk2(ull v, float& a, float& b) {
    asm("mov.b64 {%0,%1}, %2;" : "=f"(a), "=f"(b) : "l"(v));
}
__device__ __forceinline__ ull pdup(float x) {
    ull r; asm("mov.b64 %0, {%1,%1};" : "=l"(r) : "f"(x)); return r;
}
__device__ __forceinline__ ull pfma(ull a, ull b, ull c) {
    ull r; asm("fma.rn.f32x2 %0, %1, %2, %3;" : "=l"(r) : "l"(a), "l"(b), "l"(c)); return r;
}
__device__ __forceinline__ ull pmul(ull a, ull b) {
    ull r; asm("mul.rn.f32x2 %0, %1, %2;" : "=l"(r) : "l"(a), "l"(b)); return r;
}
__device__ __forceinline__ ull padd(ull a, ull b) {
    ull r; asm("add.rn.f32x2 %0, %1, %2;" : "=l"(r) : "l"(a), "l"(b)); return r;
}

// ============================================================================
// Prep: fold learned weights into Wtp and the 9 context matrices.
// m: 0:K0+K1+K2+K3  1:K0+K2  2:K0+K1  3:K0  4:K1+K3  5:K1  6:K2+K3  7:K2  8:K3
// ============================================================================
__global__ void prep_kernel(const float* __restrict__ sh,
                            const float* __restrict__ cg_agg,
                            const float* __restrict__ cg_tp,
                            const float* __restrict__ w_agg,
                            const float* __restrict__ w_tp) {
    int gtid = blockIdx.x * blockDim.x + threadIdx.x;
    int nthr = gridDim.x * blockDim.x;
    for (int idx = gtid; idx < CF * CF * IPAD; idx += nthr) {
        int k = idx / (CF * IPAD);
        int r = idx - k * CF * IPAD;
        int j = r / IPAD;
        int i = r - j * IPAD;
        float v = 0.f;
        if (i < CF) {
            #pragma unroll
            for (int p = 0; p < 8; p++)
                v += w_tp[p] * cg_tp[((p * CF + i) * CF + j) * CF + k];
        }
        gWtp[idx] = v;
    }
    for (int idx = gtid; idx < CF * KPAD; idx += nthr) {
        int i = idx / KPAD;
        int k = idx - i * KPAD;
        float K0 = 0.f, K1 = 0.f, K2 = 0.f, K3 = 0.f;
        if (k < CF) {
            #pragma unroll
            for (int s = 0; s < 6; s++) {
                float wa = 0.f;
                #pragma unroll
                for (int p = 0; p < 6; p++)
                    wa += w_agg[p] * cg_agg[((p * CF + i) * 6 + s) * CF + k];
                K0 += wa * sh[0 * 6 + s];
                K1 += wa * sh[1 * 6 + s];
                K2 += wa * sh[2 * 6 + s];
                K3 += wa * sh[3 * 6 + s];
            }
        }
        gK[(0 * CF + i) * KPAD + k] = K0 + K1 + K2 + K3;
        gK[(1 * CF + i) * KPAD + k] = K0 + K2;
        gK[(2 * CF + i) * KPAD + k] = K0 + K1;
        gK[(3 * CF + i) * KPAD + k] = K0;
        gK[(4 * CF + i) * KPAD + k] = K1 + K3;
        gK[(5 * CF + i) * KPAD + k] = K1;
        gK[(6 * CF + i) * KPAD + k] = K2 + K3;
        gK[(7 * CF + i) * KPAD + k] = K2;
        gK[(8 * CF + i) * KPAD + k] = K3;
    }
}

// Context accumulation pass: ctx2[CAT][*] += src[i] * sK[m][i][*]
template <int CAT>
__device__ __forceinline__ void ctx_pass(ull (&ctx2)[4][11], const ulonglong2* sK2,
                                         const float* src, int m) {
    #pragma unroll 2
    for (int i = 0; i < CF; i++) {
        ull fi2 = pdup(src[i]);
        const ulonglong2* row = sK2 + (m * CF + i) * 6;
        #pragma unroll
        for (int c = 0; c < 5; c++) {
            ulonglong2 t = row[c];
            ctx2[CAT][2 * c]     = pfma(fi2, t.x, ctx2[CAT][2 * c]);
            ctx2[CAT][2 * c + 1] = pfma(fi2, t.y, ctx2[CAT][2 * c + 1]);
        }
        ull t10 = row[5].x;
        ctx2[CAT][10] = pfma(fi2, t10, ctx2[CAT][10]);
    }
}

// ============================================================================
// Main kernel (R9 champion + mov-free scalar cat-accumulation):
//   smem = sW (45.4KB) + sK (18.6KB) + stage (44.5KB) + tables (2.8KB)
//        = 111.2KB -> 2 blocks/SM.
//   Bilinear per (k,j): 6 LDS.128 + 11 FFMA2 + padd + scalar fadd +
//   4 scalar FFMA (ctx regs as direct operands) -- zero pdup movs.
//   Drain: table-driven, no div, no LDG (residual folded into the stage).
// ============================================================================
__global__ void __launch_bounds__(NT, 2)
main_kernel(const float* __restrict__ f4, const float* __restrict__ f6,
            float* __restrict__ out, int H, int W) {
    extern __shared__ float smem[];
    float* sW = smem;                      // CF*CF*IPAD
    float* sK = smem + CF * CF * IPAD;     // NM*CF*KPAD
    float* stg = sK + NM * CF * KPAD;      // NT*89 (stride 89 -> conflict-free)
    unsigned short* tbl4 = (unsigned short*)(stg + NT * 89);  // 576 entries
    unsigned short* tbl6 = tbl4 + 576;                        // 832 entries
    const int tid = threadIdx.x;

    for (int idx = tid; idx < CF * CF * IPAD; idx += NT) sW[idx] = gWtp[idx];
    for (int idx = tid; idx < NM * CF * KPAD; idx += NT) sK[idx] = gK[idx];
    // index tables: stage offset for each element of one hi-res row image
    for (int ee = tid; ee < 576; ee += NT) {
        int px = ee / 9;
        int c = ee - px * 9;
        int b = px & 3;
        int lxr = px >> 2;
        int cat = (b < 3) ? 0 : 1;   // a==3 rows: same entry + 44 (cat 2/3)
        tbl4[ee] = (unsigned short)(lxr * 89 + cat * CF + c);
    }
    for (int ee = tid; ee < 832; ee += NT) {
        int px = ee / 13;
        int c = ee - px * 13;
        int b = px & 3;
        int lxr = px >> 2;
        int cat = (b < 3) ? 0 : 1;
        tbl6[ee] = (unsigned short)(lxr * 89 + cat * CF + 9 + c);
    }
    __syncthreads();

    const int tiles_x = W / TILE_W;
    const int tx0 = (blockIdx.x % tiles_x) * TILE_W;
    const int ty0 = (blockIdx.x / tiles_x) * TILE_H;
    const int lx = tid % TILE_W;
    const int ly = tid / TILE_W;
    const int w0 = tx0 + lx;
    const int h0 = ty0 + ly;
    const int wR = min(w0 + 1, W - 1);
    const int hD = min(h0 + 1, H - 1);
    const int p00 = h0 * W + w0;
    const int p01 = h0 * W + wR;
    const int p10 = hD * W + w0;
    const int p11 = hD * W + wR;

    // ---- preload features: self -> packed regs, all 4 sources -> per-thread stage ----
    float* myst = stg + tid * 89;
    ull f2[11];
    {
        float xv[CF];
        #pragma unroll
        for (int c = 0; c < CF; c++) {
            xv[c] = (c < 9) ? f4[p00 * 9 + c] : f6[p00 * 13 + (c - 9)];
            myst[c] = xv[c];
        }
        #pragma unroll
        for (int kk = 0; kk < 11; kk++) f2[kk] = pk2(xv[2 * kk], xv[2 * kk + 1]);
        #pragma unroll
        for (int c = 0; c < CF; c++) {
            myst[1 * CF + c] = (c < 9) ? f4[p01 * 9 + c] : f6[p01 * 13 + (c - 9)];
            myst[2 * CF + c] = (c < 9) ? f4[p10 * 9 + c] : f6[p10 * 13 + (c - 9)];
            myst[3 * CF + c] = (c < 9) ? f4[p11 * 9 + c] : f6[p11 * 13 + (c - 9)];
        }
    }

    // ---- 4 context vectors (cat 0:interior 1:right-edge 2:bottom-edge 3:corner) ----
    ull ctx2[4][11];
    #pragma unroll
    for (int c4 = 0; c4 < 4; c4++)
        #pragma unroll
        for (int kk = 0; kk < 11; kk++) ctx2[c4][kk] = 0ULL;

    const ulonglong2* sK2 = (const ulonglong2*)sK;
    ctx_pass<0>(ctx2, sK2, myst, 0);
    ctx_pass<1>(ctx2, sK2, myst, 1);
    ctx_pass<2>(ctx2, sK2, myst, 2);
    ctx_pass<3>(ctx2, sK2, myst, 3);
    ctx_pass<1>(ctx2, sK2, myst + CF, 4);
    ctx_pass<3>(ctx2, sK2, myst + CF, 5);
    ctx_pass<2>(ctx2, sK2, myst + 2 * CF, 6);
    ctx_pass<3>(ctx2, sK2, myst + 2 * CF, 7);
    ctx_pass<3>(ctx2, sK2, myst + 3 * CF, 8);

    // unpack ctx to 88 scalar regs (upk2 aliases to reg pairs -> free)
    float ctx[4][CF];
    #pragma unroll
    for (int c4 = 0; c4 < 4; c4++)
        #pragma unroll
        for (int kk = 0; kk < 11; kk++) {
            float a, b;
            upk2(ctx2[c4][kk], a, b);
            ctx[c4][2 * kk] = a;
            ctx[c4][2 * kk + 1] = b;
        }

    // ---- bilinear: out_cat[k] = sum_j ctx[cat][j]*(sum_i f[i]*W[k][j][i]) + f[k] ----
    const ulonglong2* sW2 = (const ulonglong2*)sW;
    #pragma unroll 1
    for (int k = 0; k < CF; k++) {
        float o0 = 0.f, o1 = 0.f, o2 = 0.f, o3 = 0.f;
        const ulonglong2* wbase = sW2 + k * (CF * 6);
        #pragma unroll
        for (int j = 0; j < CF; j++) {
            const ulonglong2* wr = wbase + j * 6;
            ulonglong2 t0 = wr[0], t1 = wr[1], t2 = wr[2];
            ull va = pmul(f2[0], t0.x);
            ull vb = pmul(f2[1], t0.y);
            va = pfma(f2[2], t1.x, va);
            vb = pfma(f2[3], t1.y, vb);
            va = pfma(f2[4], t2.x, va);
            vb = pfma(f2[5], t2.y, vb);
            ulonglong2 t3 = wr[3], t4 = wr[4];
            ull t10 = wr[5].x;
            va = pfma(f2[6], t3.x, va);
            vb = pfma(f2[7], t3.y, vb);
            va = pfma(f2[8], t4.x, va);
            vb = pfma(f2[9], t4.y, vb);
            va = pfma(f2[10], t10, va);
            ull vp = padd(va, vb);
            float a, b;
            upk2(vp, a, b);          // free: pair aliasing
            float v = a + b;         // 1 scalar fadd
            o0 += v * ctx[0][j];     // 4 scalar FFMA, ctx regs direct operands
            o1 += v * ctx[1][j];
            o2 += v * ctx[2][j];
            o3 += v * ctx[3][j];
        }
        // residual fold: self feature k is still resident in myst[k]
        float xk = myst[k];
        myst[0 * CF + k] = o0 + xk;
        myst[1 * CF + k] = o1 + xk;
        myst[2 * CF + k] = o2 + xk;
        myst[3 * CF + k] = o3 + xk;
    }
    __syncthreads();

    // ---- table-driven drain: pure smem->gmem copy, no div, no LDG ----
    const int Wr = W * 4;
    {   // out4: 64 px * 9 floats = 144 float4 per hi-res row
        const int QR = 144;
        for (int idx = tid; idx < TILE_H * 4 * QR; idx += NT) {
            int y = idx / QR;
            int q = idx - y * QR;
            int py = y >> 2;
            int base = py * (TILE_W * 89) + (((y & 3) == 3) ? 2 * CF : 0);
            ushort4 tb = *(const ushort4*)(tbl4 + q * 4);
            float4 v = make_float4(stg[base + tb.x], stg[base + tb.y],
                                   stg[base + tb.z], stg[base + tb.w]);
            int gy = ty0 * 4 + y;
            float4* dst = (float4*)(out + ((size_t)gy * Wr + (size_t)tx0 * 4) * 9);
            dst[q] = v;
        }
    }
    {   // out6: 64 px * 13 floats = 208 float4 per hi-res row
        const size_t N9 = (size_t)H * W * 16 * 9;
        const int QR = 208;
        for (int idx = tid; idx < TILE_H * 4 * QR; idx += NT) {
            int y = idx / QR;
            int q = idx - y * QR;
            int py = y >> 2;
            int base = py * (TILE_W * 89) + (((y & 3) == 3) ? 2 * CF : 0);
            ushort4 tb = *(const ushort4*)(tbl6 + q * 4);
            float4 v = make_float4(stg[base + tb.x], stg[base + tb.y],
                                   stg[base + tb.z], stg[base + tb.w]);
            int gy = ty0 * 4 + y;
            float4* dst = (float4*)(out + N9 + ((size_t)gy * Wr + (size_t)tx0 * 4) * 13);
            dst[q] = v;
        }
    }
}

extern "C" void kernel_launch(void* const* d_in, const int* in_sizes, int n_in,
                              void* d_out, int out_size) {
    const float* f4     = (const float*)d_in[0];
    const float* f6     = (const float*)d_in[1];
    const float* sh     = (const float*)d_in[2];
    const float* cg_agg = (const float*)d_in[3];
    const float* cg_tp  = (const float*)d_in[4];
    const float* w_agg  = (const float*)d_in[5];
    const float* w_tp   = (const float*)d_in[6];
    float* out = (float*)d_out;

    int HW = in_sizes[0] / 9;
    int W = (int)(sqrt((double)HW) + 0.5);
    int H = HW / W;

    prep_kernel<<<96, 128>>>(sh, cg_agg, cg_tp, w_agg, w_tp);

    // floats: sW 11616 + sK 4752 + stage 11392, then 1408 ushorts (704 floats)
    int smemB = (CF * CF * IPAD + NM * CF * KPAD + NT * 89 + 704) * (int)sizeof(float);
    cudaFuncSetAttribute(main_kernel, cudaFuncAttributeMaxDynamicSharedMemorySize, smemB);
    int nblocks = HW / NT;
    main_kernel<<<nblocks, NT, smemB>>>(f4, f6, out, H, W);
}